// round 3
// baseline (speedup 1.0000x reference)
#include <cuda_runtime.h>
#include <cstdint>

#define BB 4
#define NN 8192
#define SS 2048
#define C1V 128
#define C2V 256
#define CCV 384           // C1+C2
#define JJ (BB*NN)        // 32768
#define NRB (JJ/128)      // 256 row blocks for GEMMs

// ---------------- device scratch (static, allocation-free) ----------------
__device__ float g_p2t[BB*SS*C2V];                 // points2 transposed (B,S,C2)  8.4MB
__device__ int   g_idx[JJ*3];
__device__ float g_wgt[JJ*3];
__device__ float g_xcat[(size_t)JJ*CCV];           // (J, 384) point-major         50MB
__device__ float g_y0[(size_t)JJ*256];             // layer0 pre-BN                33.5MB
__device__ float g_y1[(size_t)JJ*128];             // layer1 pre-BN                16.8MB
__device__ float g_p0s[NRB*256], g_p0q[NRB*256];   // partial sums / sumsq (layer0)
__device__ float g_p1s[NRB*128], g_p1q[NRB*128];
__device__ float g_sc0[256], g_sh0[256];
__device__ float g_sc1[128], g_sh1[128];

// ---------------- packed f32x2 FMA ----------------
__device__ __forceinline__ float2 ffma2(float2 a, float2 b, float2 c) {
    unsigned long long ua, ub, uc, ud;
    memcpy(&ua, &a, 8); memcpy(&ub, &b, 8); memcpy(&uc, &c, 8);
    asm("fma.rn.f32x2 %0, %1, %2, %3;" : "=l"(ud) : "l"(ua), "l"(ub), "l"(uc));
    float2 r; memcpy(&r, &ud, 8);
    return r;
}

// ---------------- K1: 3-NN + weights ----------------
__global__ void knn_kernel(const float* __restrict__ xyz1, const float* __restrict__ xyz2) {
    __shared__ float4 pts[SS];
    const int b = blockIdx.y;
    const float* x2 = xyz2 + (size_t)b * 3 * SS;
    for (int s = threadIdx.x; s < SS; s += blockDim.x) {
        float x = x2[s], y = x2[SS + s], z = x2[2 * SS + s];
        pts[s] = make_float4(x, y, z, x * x + y * y + z * z);
    }
    __syncthreads();
    const int n = blockIdx.x * blockDim.x + threadIdx.x;
    const float* x1 = xyz1 + (size_t)b * 3 * NN;
    const float qx = x1[n], qy = x1[NN + n], qz = x1[2 * NN + n];
    const float qn = qx * qx + qy * qy + qz * qz;
    float d0 = 3.4e38f, d1 = 3.4e38f, d2 = 3.4e38f;
    int   i0 = 0, i1 = 0, i2 = 0;
#pragma unroll 4
    for (int s = 0; s < SS; ++s) {
        float4 p = pts[s];
        float dot = fmaf(qx, p.x, fmaf(qy, p.y, qz * p.z));
        float d = fmaf(-2.f, dot, qn + p.w);
        if (d < d2) {
            if (d < d1) {
                d2 = d1; i2 = i1;
                if (d < d0) { d1 = d0; i1 = i0; d0 = d; i0 = s; }
                else        { d1 = d;  i1 = s; }
            } else { d2 = d; i2 = s; }
        }
    }
    float r0 = 1.f / (d0 + 1e-8f), r1 = 1.f / (d1 + 1e-8f), r2 = 1.f / (d2 + 1e-8f);
    float inv = 1.f / (r0 + r1 + r2);
    const int j = b * NN + n;
    g_idx[j * 3 + 0] = i0; g_idx[j * 3 + 1] = i1; g_idx[j * 3 + 2] = i2;
    g_wgt[j * 3 + 0] = r0 * inv; g_wgt[j * 3 + 1] = r1 * inv; g_wgt[j * 3 + 2] = r2 * inv;
}

// ---------------- K2: (B,C,L) channel-major -> point-major rows ----------------
// dst[(b*L + l)*rowlen + coff + c] = src[(b*Cdim + c)*L + l]
__global__ void transpose_to_rows(const float* __restrict__ src, float* __restrict__ dst,
                                  int Cdim, int L, int rowlen, int coff) {
    __shared__ float tile[32][33];
    const int b = blockIdx.z;
    const int l0 = blockIdx.x * 32, c0 = blockIdx.y * 32;
    for (int i = threadIdx.y; i < 32; i += 8)
        tile[i][threadIdx.x] = src[((size_t)b * Cdim + c0 + i) * L + l0 + threadIdx.x];
    __syncthreads();
    for (int i = threadIdx.y; i < 32; i += 8)
        dst[((size_t)b * L + l0 + i) * rowlen + coff + c0 + threadIdx.x] = tile[threadIdx.x][i];
}

// ---------------- K3: interpolation into xcat[:, 128:384] ----------------
__global__ void interp_kernel() {
    __shared__ int   sidx[24];
    __shared__ float swgt[24];
    const int j0 = blockIdx.x * 8;
    const int t = threadIdx.x;
    if (t < 24)               sidx[t]      = g_idx[(size_t)j0 * 3 + t];
    if (t >= 32 && t < 56)    swgt[t - 32] = g_wgt[(size_t)j0 * 3 + (t - 32)];
    __syncthreads();
    const int c = t;  // 256 threads = 256 channels
#pragma unroll
    for (int pp = 0; pp < 8; ++pp) {
        const int j = j0 + pp;
        const int b = j >> 13;  // / NN
        const float* r0 = g_p2t + ((size_t)b * SS + sidx[pp * 3 + 0]) * C2V;
        const float* r1 = g_p2t + ((size_t)b * SS + sidx[pp * 3 + 1]) * C2V;
        const float* r2 = g_p2t + ((size_t)b * SS + sidx[pp * 3 + 2]) * C2V;
        float v = swgt[pp * 3 + 0] * r0[c] + swgt[pp * 3 + 1] * r1[c] + swgt[pp * 3 + 2] * r2[c];
        g_xcat[(size_t)j * CCV + C1V + c] = v;
    }
}

// ---------------- K4/K6: GEMM (J x KDIM) @ (Cout x KDIM)^T, bias, BN partials ----------------
// Tile: 128 rows x 64 cols x 16 k. 256 threads, each computes 8x4 via f32x2 pairs.
// If ACT: A elements are transformed relu(a*scale[k]+shift[k]) at load (folded BN+ReLU).
template<int KDIM, int NCOLS, bool ACT>
__global__ void gemm_bn_kernel(const float* __restrict__ A, const float* __restrict__ W,
                               const float* __restrict__ bias, float* __restrict__ out,
                               float* __restrict__ psum, float* __restrict__ psq,
                               const float* __restrict__ scale, const float* __restrict__ shift) {
    __shared__ float  As[16][128];   // [k][row]
    __shared__ float2 Bs[16][64];    // [k][col], duplicated {b,b}
    __shared__ float  reds[16][64];
    __shared__ float  redq[16][64];

    const int t  = threadIdx.x;
    const int tx = t & 15, ty = t >> 4;
    const int j0 = blockIdx.x * 128;
    const int o0 = blockIdx.y * 64;

    float2 acc[4][4];
#pragma unroll
    for (int r = 0; r < 4; ++r)
#pragma unroll
        for (int c = 0; c < 4; ++c) acc[r][c] = make_float2(0.f, 0.f);

    for (int k0 = 0; k0 < KDIM; k0 += 16) {
        // load A tile: 128x16 = 512 float4
#pragma unroll
        for (int ss = 0; ss < 2; ++ss) {
            int f = t + ss * 256;
            int row = f >> 2, kq = (f & 3) * 4;
            float4 v = *(const float4*)(A + (size_t)(j0 + row) * KDIM + k0 + kq);
            if (ACT) {
                v.x = fmaxf(fmaf(v.x, scale[k0 + kq + 0], shift[k0 + kq + 0]), 0.f);
                v.y = fmaxf(fmaf(v.y, scale[k0 + kq + 1], shift[k0 + kq + 1]), 0.f);
                v.z = fmaxf(fmaf(v.z, scale[k0 + kq + 2], shift[k0 + kq + 2]), 0.f);
                v.w = fmaxf(fmaf(v.w, scale[k0 + kq + 3], shift[k0 + kq + 3]), 0.f);
            }
            As[kq + 0][row] = v.x; As[kq + 1][row] = v.y;
            As[kq + 2][row] = v.z; As[kq + 3][row] = v.w;
        }
        // load W tile: 64x16 = 256 float4 (one per thread), duplicate pairs
        {
            int row = t >> 2, kq = (t & 3) * 4;
            float4 v = *(const float4*)(W + (size_t)(o0 + row) * KDIM + k0 + kq);
            Bs[kq + 0][row] = make_float2(v.x, v.x);
            Bs[kq + 1][row] = make_float2(v.y, v.y);
            Bs[kq + 2][row] = make_float2(v.z, v.z);
            Bs[kq + 3][row] = make_float2(v.w, v.w);
        }
        __syncthreads();
#pragma unroll
        for (int kk = 0; kk < 16; ++kk) {
            float2 a[4], b[4];
            const float2* ap = (const float2*)&As[kk][ty * 8];
            const float2* bp = &Bs[kk][tx * 4];
#pragma unroll
            for (int r = 0; r < 4; ++r) a[r] = ap[r];
#pragma unroll
            for (int c = 0; c < 4; ++c) b[c] = bp[c];
#pragma unroll
            for (int r = 0; r < 4; ++r)
#pragma unroll
                for (int c = 0; c < 4; ++c) acc[r][c] = ffma2(a[r], b[c], acc[r][c]);
        }
        __syncthreads();
    }

    // epilogue: bias, store, per-column partial sums
    float v[8][4];
#pragma unroll
    for (int r = 0; r < 4; ++r)
#pragma unroll
        for (int c = 0; c < 4; ++c) {
            float bv = bias[o0 + tx * 4 + c];
            v[2 * r + 0][c] = acc[r][c].x + bv;
            v[2 * r + 1][c] = acc[r][c].y + bv;
        }
#pragma unroll
    for (int r = 0; r < 8; ++r) {
        float4 w4 = make_float4(v[r][0], v[r][1], v[r][2], v[r][3]);
        *(float4*)(out + (size_t)(j0 + ty * 8 + r) * NCOLS + o0 + tx * 4) = w4;
    }
#pragma unroll
    for (int c = 0; c < 4; ++c) {
        float s = 0.f, q = 0.f;
#pragma unroll
        for (int r = 0; r < 8; ++r) { s += v[r][c]; q = fmaf(v[r][c], v[r][c], q); }
        reds[ty][tx * 4 + c] = s;
        redq[ty][tx * 4 + c] = q;
    }
    __syncthreads();
    if (t < 64) {
        float s = 0.f, q = 0.f;
#pragma unroll
        for (int yy = 0; yy < 16; ++yy) { s += reds[yy][t]; q += redq[yy][t]; }
        psum[(size_t)blockIdx.x * NCOLS + o0 + t] = s;
        psq [(size_t)blockIdx.x * NCOLS + o0 + t] = q;
    }
}

// ---------------- K5/K7: finalize BN scale/shift (deterministic order) ----------------
__global__ void finalize_bn(const float* __restrict__ psum, const float* __restrict__ psq,
                            int C, const float* __restrict__ gamma, const float* __restrict__ beta,
                            float* __restrict__ scale, float* __restrict__ shift) {
    const int o = threadIdx.x;
    if (o >= C) return;
    float s = 0.f, q = 0.f;
    for (int r = 0; r < NRB; ++r) { s += psum[(size_t)r * C + o]; q += psq[(size_t)r * C + o]; }
    const float invn = 1.f / (float)JJ;
    float m = s * invn;
    float var = q * invn - m * m;
    float sc = gamma[o] * rsqrtf(var + 1e-5f);
    scale[o] = sc;
    shift[o] = beta[o] - m * sc;
}

// ---------------- K8: BN+ReLU on y1 + transpose to (B,128,N) ----------------
__global__ void output_kernel(float* __restrict__ out) {
    __shared__ float tile[32][33];
    const int b = blockIdx.z;
    const int n0 = blockIdx.x * 32, p0 = blockIdx.y * 32;
    const int tx = threadIdx.x;
    for (int i = threadIdx.y; i < 32; i += 8) {
        int p = p0 + tx, n = n0 + i;
        float v = g_y1[((size_t)b * NN + n) * 128 + p];
        v = fmaxf(fmaf(v, g_sc1[p], g_sh1[p]), 0.f);
        tile[i][tx] = v;
    }
    __syncthreads();
    for (int i = threadIdx.y; i < 8 * 4; i += 8)
        ;
    for (int i = threadIdx.y; i < 32; i += 8)
        out[((size_t)(b * 128) + p0 + i) * NN + n0 + tx] = tile[tx][i];
}

// ---------------- launch ----------------
extern "C" void kernel_launch(void* const* d_in, const int* in_sizes, int n_in,
                              void* d_out, int out_size) {
    const float* xyz1    = (const float*)d_in[0];
    const float* xyz2    = (const float*)d_in[1];
    const float* points1 = (const float*)d_in[2];
    const float* points2 = (const float*)d_in[3];
    const float* w0      = (const float*)d_in[4];
    const float* b0      = (const float*)d_in[5];
    const float* gamma0  = (const float*)d_in[6];
    const float* beta0   = (const float*)d_in[7];
    const float* w1      = (const float*)d_in[8];
    const float* b1      = (const float*)d_in[9];
    const float* gamma1  = (const float*)d_in[10];
    const float* beta1   = (const float*)d_in[11];
    float* out = (float*)d_out;

    float *p2t, *xcat, *y0, *y1, *p0s, *p0q, *p1s, *p1q, *sc0, *sh0, *sc1, *sh1;
    int* idxp;
    float* wgtp;
    cudaGetSymbolAddress((void**)&p2t,  g_p2t);
    cudaGetSymbolAddress((void**)&idxp, g_idx);
    cudaGetSymbolAddress((void**)&wgtp, g_wgt);
    cudaGetSymbolAddress((void**)&xcat, g_xcat);
    cudaGetSymbolAddress((void**)&y0,   g_y0);
    cudaGetSymbolAddress((void**)&y1,   g_y1);
    cudaGetSymbolAddress((void**)&p0s,  g_p0s);
    cudaGetSymbolAddress((void**)&p0q,  g_p0q);
    cudaGetSymbolAddress((void**)&p1s,  g_p1s);
    cudaGetSymbolAddress((void**)&p1q,  g_p1q);
    cudaGetSymbolAddress((void**)&sc0,  g_sc0);
    cudaGetSymbolAddress((void**)&sh0,  g_sh0);
    cudaGetSymbolAddress((void**)&sc1,  g_sc1);
    cudaGetSymbolAddress((void**)&sh1,  g_sh1);

    // K1: 3-NN
    knn_kernel<<<dim3(NN / 256, BB), 256>>>(xyz1, xyz2);
    // K2a: points2 -> (B,S,C2)
    transpose_to_rows<<<dim3(SS / 32, C2V / 32, BB), dim3(32, 8)>>>(points2, p2t, C2V, SS, C2V, 0);
    // K2b: points1 -> xcat[:, 0:128]
    transpose_to_rows<<<dim3(NN / 32, C1V / 32, BB), dim3(32, 8)>>>(points1, xcat, C1V, NN, CCV, 0);
    // K3: interpolation -> xcat[:, 128:384]
    interp_kernel<<<JJ / 8, 256>>>();
    // K4: GEMM0 + bias + BN partials
    gemm_bn_kernel<CCV, 256, false><<<dim3(NRB, 4), 256>>>(xcat, w0, b0, y0, p0s, p0q, nullptr, nullptr);
    // K5: BN0 finalize
    finalize_bn<<<1, 256>>>(p0s, p0q, 256, gamma0, beta0, sc0, sh0);
    // K6: GEMM1 with folded BN0+ReLU on input, + bias + BN partials
    gemm_bn_kernel<256, 128, true><<<dim3(NRB, 2), 256>>>(y0, w1, b1, y1, p1s, p1q, sc0, sh0);
    // K7: BN1 finalize
    finalize_bn<<<1, 128>>>(p1s, p1q, 128, gamma1, beta1, sc1, sh1);
    // K8: BN1+ReLU + transpose to (B,128,N)
    output_kernel<<<dim3(NN / 32, 128 / 32, BB), dim3(32, 8)>>>(out);
}

// round 5
// speedup vs baseline: 1.9730x; 1.9730x over previous
#include <cuda_runtime.h>
#include <cstdint>

#define BB 4
#define NN 8192
#define SS 2048
#define C1V 128
#define C2V 256
#define CCV 384           // C1+C2
#define JJ (BB*NN)        // 32768
#define NRB (JJ/128)      // 256 row blocks

// ---------------- device scratch ----------------
__device__ float g_p2t[BB*SS*C2V];                 // points2 transposed (B,S,C2)
__device__ int   g_idx[JJ*3];
__device__ float g_wgt[JJ*3];
__device__ float g_xcat[(size_t)JJ*CCV];           // (J,384) point-major, tf32-rounded
__device__ float g_y0[(size_t)JJ*256];             // layer0 pre-BN (f32)
__device__ float g_y1[(size_t)JJ*128];             // layer1 pre-BN (f32)
__device__ float g_w0t[256*384];                   // tf32-rounded weights
__device__ float g_w1t[128*256];
__device__ float g_p0s[NRB*256], g_p0q[NRB*256];
__device__ float g_p1s[NRB*128], g_p1q[NRB*128];
__device__ float g_sc0[256], g_sh0[256];
__device__ float g_sc1[128], g_sh1[128];

// ---------------- tf32 helpers (base ISA only) ----------------
__device__ __forceinline__ uint32_t f2tf32(float x) {
    uint32_t r;
    asm("cvt.rna.tf32.f32 %0, %1;" : "=r"(r) : "f"(x));
    return r;
}
__device__ __forceinline__ void mma16n8k8(float* c, const uint32_t* a, const uint32_t* b) {
    asm volatile(
        "mma.sync.aligned.m16n8k8.row.col.f32.tf32.tf32.f32 "
        "{%0,%1,%2,%3}, {%4,%5,%6,%7}, {%8,%9}, {%0,%1,%2,%3};"
        : "+f"(c[0]), "+f"(c[1]), "+f"(c[2]), "+f"(c[3])
        : "r"(a[0]), "r"(a[1]), "r"(a[2]), "r"(a[3]), "r"(b[0]), "r"(b[1]));
}

// ---------------- K1: 3-NN + weights ----------------
__global__ void knn_kernel(const float* __restrict__ xyz1, const float* __restrict__ xyz2) {
    __shared__ float4 pts[SS];
    const int b = blockIdx.y;
    const float* x2 = xyz2 + (size_t)b * 3 * SS;
    for (int s = threadIdx.x; s < SS; s += blockDim.x) {
        float x = x2[s], y = x2[SS + s], z = x2[2 * SS + s];
        pts[s] = make_float4(x, y, z, x * x + y * y + z * z);
    }
    __syncthreads();
    const int n = blockIdx.x * blockDim.x + threadIdx.x;
    const float* x1 = xyz1 + (size_t)b * 3 * NN;
    const float qx = x1[n], qy = x1[NN + n], qz = x1[2 * NN + n];
    const float qn = qx * qx + qy * qy + qz * qz;
    float d0 = 3.4e38f, d1 = 3.4e38f, d2 = 3.4e38f;
    int   i0 = 0, i1 = 0, i2 = 0;
#pragma unroll 4
    for (int s = 0; s < SS; ++s) {
        float4 p = pts[s];
        float dot = fmaf(qx, p.x, fmaf(qy, p.y, qz * p.z));
        float d = fmaf(-2.f, dot, qn + p.w);
        if (d < d2) {
            if (d < d1) {
                d2 = d1; i2 = i1;
                if (d < d0) { d1 = d0; i1 = i0; d0 = d; i0 = s; }
                else        { d1 = d;  i1 = s; }
            } else { d2 = d; i2 = s; }
        }
    }
    float r0 = 1.f / (d0 + 1e-8f), r1 = 1.f / (d1 + 1e-8f), r2 = 1.f / (d2 + 1e-8f);
    float inv = 1.f / (r0 + r1 + r2);
    const int j = b * NN + n;
    g_idx[j * 3 + 0] = i0; g_idx[j * 3 + 1] = i1; g_idx[j * 3 + 2] = i2;
    g_wgt[j * 3 + 0] = r0 * inv; g_wgt[j * 3 + 1] = r1 * inv; g_wgt[j * 3 + 2] = r2 * inv;
}

// ---------------- K2: (B,C,L) -> point-major rows (optionally tf32-rounded) ----------------
template<bool RND>
__global__ void transpose_to_rows(const float* __restrict__ src, float* __restrict__ dst,
                                  int Cdim, int L, int rowlen, int coff) {
    __shared__ float tile[32][33];
    const int b = blockIdx.z;
    const int l0 = blockIdx.x * 32, c0 = blockIdx.y * 32;
    for (int i = threadIdx.y; i < 32; i += 8)
        tile[i][threadIdx.x] = src[((size_t)b * Cdim + c0 + i) * L + l0 + threadIdx.x];
    __syncthreads();
    for (int i = threadIdx.y; i < 32; i += 8) {
        float v = tile[threadIdx.x][i];
        if (RND) v = __uint_as_float(f2tf32(v));
        dst[((size_t)b * L + l0 + i) * rowlen + coff + c0 + threadIdx.x] = v;
    }
}

// ---------------- K3: interpolation into xcat[:, 128:384] (tf32-rounded) ----------------
__global__ void interp_kernel() {
    __shared__ int   sidx[24];
    __shared__ float swgt[24];
    const int j0 = blockIdx.x * 8;
    const int t = threadIdx.x;
    if (t < 24)               sidx[t]      = g_idx[(size_t)j0 * 3 + t];
    if (t >= 32 && t < 56)    swgt[t - 32] = g_wgt[(size_t)j0 * 3 + (t - 32)];
    __syncthreads();
    const int c = t;
#pragma unroll
    for (int pp = 0; pp < 8; ++pp) {
        const int j = j0 + pp;
        const int b = j >> 13;
        const float* r0 = g_p2t + ((size_t)b * SS + sidx[pp * 3 + 0]) * C2V;
        const float* r1 = g_p2t + ((size_t)b * SS + sidx[pp * 3 + 1]) * C2V;
        const float* r2 = g_p2t + ((size_t)b * SS + sidx[pp * 3 + 2]) * C2V;
        float v = swgt[pp * 3 + 0] * r0[c] + swgt[pp * 3 + 1] * r1[c] + swgt[pp * 3 + 2] * r2[c];
        g_xcat[(size_t)j * CCV + C1V + c] = __uint_as_float(f2tf32(v));
    }
}

// ---------------- K-prep: round weights to tf32 ----------------
__global__ void prep_w(const float* __restrict__ w0, const float* __restrict__ w1) {
    int i = blockIdx.x * 256 + threadIdx.x;
    if (i < 256 * 384) g_w0t[i] = __uint_as_float(f2tf32(w0[i]));
    if (i < 128 * 256) g_w1t[i] = __uint_as_float(f2tf32(w1[i]));
}

// ---------------- mma.sync tf32 GEMM: (J x KDIM) @ (Cout x KDIM)^T + bias ----------------
// Block tile 128x64, 8 warps (warp tile 32x32), k-chunk 16.
// Smem padded to stride 20 floats -> fragment LDS (addr = 20*r + k) is bank-conflict-free.
// If ACT: A elements get relu(a*scale[k]+shift[k]) then tf32 rounding at load.
#define STRD 20
template<int KDIM, int NCOLS, bool ACT>
__global__ __launch_bounds__(256) void gemm_mma(
    const float* __restrict__ A, const float* __restrict__ W,
    const float* __restrict__ bias, float* __restrict__ out,
    const float* __restrict__ scale, const float* __restrict__ shift)
{
    __shared__ float As[128 * STRD];
    __shared__ float Bs[64 * STRD];

    const int t = threadIdx.x, wid = t >> 5, lane = t & 31;
    const int j0 = blockIdx.x * 128;
    const int o0 = blockIdx.y * 64;
    const int wm = (wid >> 1) * 32;       // warp m offset (0..96)
    const int wn = (wid & 1) * 32;        // warp n offset (0 or 32)
    const int lr = lane >> 2, lk = lane & 3;

    float acc[2][4][4];
#pragma unroll
    for (int mt = 0; mt < 2; ++mt)
#pragma unroll
        for (int nt = 0; nt < 4; ++nt)
#pragma unroll
            for (int i = 0; i < 4; ++i) acc[mt][nt][i] = 0.f;

    // global-load indexing
    const int arow = t >> 2, akq = (t & 3) * 4;           // A: 2 float4/thread
    const int brow = t >> 2, bkq = (t & 3) * 4;           // B: 1 float4/thread (rows 0..63)

    float4 pa0, pa1, pb;
    {
        const float* a0 = A + (size_t)(j0 + arow) * KDIM + akq;
        pa0 = *(const float4*)a0;
        pa1 = *(const float4*)(a0 + (size_t)64 * KDIM);
        pb  = *(const float4*)(W + (size_t)(o0 + brow) * KDIM + bkq);
    }

    constexpr int NCHUNK = KDIM / 16;
    for (int c = 0; c < NCHUNK; ++c) {
        // transform+store staged regs to smem
        float4 va0 = pa0, va1 = pa1;
        if (ACT) {
            const int kb = c * 16 + akq;
            float s0 = scale[kb], s1 = scale[kb+1], s2 = scale[kb+2], s3 = scale[kb+3];
            float h0 = shift[kb], h1 = shift[kb+1], h2 = shift[kb+2], h3 = shift[kb+3];
            va0.x = __uint_as_float(f2tf32(fmaxf(fmaf(va0.x, s0, h0), 0.f)));
            va0.y = __uint_as_float(f2tf32(fmaxf(fmaf(va0.y, s1, h1), 0.f)));
            va0.z = __uint_as_float(f2tf32(fmaxf(fmaf(va0.z, s2, h2), 0.f)));
            va0.w = __uint_as_float(f2tf32(fmaxf(fmaf(va0.w, s3, h3), 0.f)));
            va1.x = __uint_as_float(f2tf32(fmaxf(fmaf(va1.x, s0, h0), 0.f)));
            va1.y = __uint_as_float(f2tf32(fmaxf(fmaf(va1.y, s1, h1), 0.f)));
            va1.z = __uint_as_float(f2tf32(fmaxf(fmaf(va1.z, s2, h2), 0.f)));
            va1.w = __uint_as_float(f2tf32(fmaxf(fmaf(va1.w, s3, h3), 0.f)));
        }
        *(float4*)&As[arow * STRD + akq]        = va0;
        *(float4*)&As[(arow + 64) * STRD + akq] = va1;
        *(float4*)&Bs[brow * STRD + bkq]        = pb;
        __syncthreads();

        // prefetch next chunk
        if (c + 1 < NCHUNK) {
            const int k0 = (c + 1) * 16;
            const float* a0 = A + (size_t)(j0 + arow) * KDIM + k0 + akq;
            pa0 = *(const float4*)a0;
            pa1 = *(const float4*)(a0 + (size_t)64 * KDIM);
            pb  = *(const float4*)(W + (size_t)(o0 + brow) * KDIM + k0 + bkq);
        }

        // compute: two k8 steps
#pragma unroll
        for (int kk = 0; kk < 2; ++kk) {
            uint32_t af[2][4], bf[4][2];
#pragma unroll
            for (int mt = 0; mt < 2; ++mt) {
                const int r = wm + mt * 16 + lr;
                const int k = kk * 8 + lk;
                af[mt][0] = __float_as_uint(As[r * STRD + k]);
                af[mt][1] = __float_as_uint(As[(r + 8) * STRD + k]);
                af[mt][2] = __float_as_uint(As[r * STRD + k + 4]);
                af[mt][3] = __float_as_uint(As[(r + 8) * STRD + k + 4]);
            }
#pragma unroll
            for (int nt = 0; nt < 4; ++nt) {
                const int n = wn + nt * 8 + lr;
                const int k = kk * 8 + lk;
                bf[nt][0] = __float_as_uint(Bs[n * STRD + k]);
                bf[nt][1] = __float_as_uint(Bs[n * STRD + k + 4]);
            }
#pragma unroll
            for (int mt = 0; mt < 2; ++mt)
#pragma unroll
                for (int nt = 0; nt < 4; ++nt)
                    mma16n8k8(acc[mt][nt], af[mt], bf[nt]);
        }
        __syncthreads();
    }

    // epilogue: bias + store (float2 per half-tile)
#pragma unroll
    for (int mt = 0; mt < 2; ++mt) {
        const int r0 = j0 + wm + mt * 16 + lr;
#pragma unroll
        for (int nt = 0; nt < 4; ++nt) {
            const int col = o0 + wn + nt * 8 + 2 * lk;
            const float b0 = bias[col], b1 = bias[col + 1];
            float2 v0 = make_float2(acc[mt][nt][0] + b0, acc[mt][nt][1] + b1);
            float2 v1 = make_float2(acc[mt][nt][2] + b0, acc[mt][nt][3] + b1);
            *(float2*)(out + (size_t)r0 * NCOLS + col)       = v0;
            *(float2*)(out + (size_t)(r0 + 8) * NCOLS + col) = v1;
        }
    }
}

// ---------------- BN column reduce ----------------
template<int NC>
__global__ void bn_reduce(const float* __restrict__ y, float* __restrict__ psum,
                          float* __restrict__ psq) {
    const int c = threadIdx.x;
    const float* base = y + (size_t)blockIdx.x * 128 * NC;
    float s = 0.f, q = 0.f;
#pragma unroll 8
    for (int r = 0; r < 128; ++r) {
        float v = base[(size_t)r * NC + c];
        s += v; q = fmaf(v, v, q);
    }
    psum[(size_t)blockIdx.x * NC + c] = s;
    psq [(size_t)blockIdx.x * NC + c] = q;
}

// ---------------- finalize BN scale/shift ----------------
__global__ void finalize_bn(const float* __restrict__ psum, const float* __restrict__ psq,
                            int C, const float* __restrict__ gamma, const float* __restrict__ beta,
                            float* __restrict__ scale, float* __restrict__ shift) {
    const int o = threadIdx.x;
    if (o >= C) return;
    float s = 0.f, q = 0.f;
    for (int r = 0; r < NRB; ++r) { s += psum[(size_t)r * C + o]; q += psq[(size_t)r * C + o]; }
    const float invn = 1.f / (float)JJ;
    float m = s * invn;
    float var = q * invn - m * m;
    float sc = gamma[o] * rsqrtf(var + 1e-5f);
    scale[o] = sc;
    shift[o] = beta[o] - m * sc;
}

// ---------------- output: BN1+ReLU + transpose to (B,128,N) ----------------
__global__ void output_kernel(float* __restrict__ out) {
    __shared__ float tile[32][33];
    const int b = blockIdx.z;
    const int n0 = blockIdx.x * 32, p0 = blockIdx.y * 32;
    const int tx = threadIdx.x;
    for (int i = threadIdx.y; i < 32; i += 8) {
        int p = p0 + tx, n = n0 + i;
        float v = g_y1[((size_t)b * NN + n) * 128 + p];
        tile[i][tx] = fmaxf(fmaf(v, g_sc1[p], g_sh1[p]), 0.f);
    }
    __syncthreads();
    for (int i = threadIdx.y; i < 32; i += 8)
        out[((size_t)(b * 128) + p0 + i) * NN + n0 + tx] = tile[tx][i];
}

// ---------------- launch ----------------
extern "C" void kernel_launch(void* const* d_in, const int* in_sizes, int n_in,
                              void* d_out, int out_size) {
    const float* xyz1    = (const float*)d_in[0];
    const float* xyz2    = (const float*)d_in[1];
    const float* points1 = (const float*)d_in[2];
    const float* points2 = (const float*)d_in[3];
    const float* w0      = (const float*)d_in[4];
    const float* b0      = (const float*)d_in[5];
    const float* gamma0  = (const float*)d_in[6];
    const float* beta0   = (const float*)d_in[7];
    const float* w1      = (const float*)d_in[8];
    const float* b1      = (const float*)d_in[9];
    const float* gamma1  = (const float*)d_in[10];
    const float* beta1   = (const float*)d_in[11];
    float* out = (float*)d_out;

    float *p2t, *xcat, *y0, *y1, *w0t, *w1t, *p0s, *p0q, *p1s, *p1q, *sc0, *sh0, *sc1, *sh1;
    cudaGetSymbolAddress((void**)&p2t,  g_p2t);
    cudaGetSymbolAddress((void**)&xcat, g_xcat);
    cudaGetSymbolAddress((void**)&y0,   g_y0);
    cudaGetSymbolAddress((void**)&y1,   g_y1);
    cudaGetSymbolAddress((void**)&w0t,  g_w0t);
    cudaGetSymbolAddress((void**)&w1t,  g_w1t);
    cudaGetSymbolAddress((void**)&p0s,  g_p0s);
    cudaGetSymbolAddress((void**)&p0q,  g_p0q);
    cudaGetSymbolAddress((void**)&p1s,  g_p1s);
    cudaGetSymbolAddress((void**)&p1q,  g_p1q);
    cudaGetSymbolAddress((void**)&sc0,  g_sc0);
    cudaGetSymbolAddress((void**)&sh0,  g_sh0);
    cudaGetSymbolAddress((void**)&sc1,  g_sc1);
    cudaGetSymbolAddress((void**)&sh1,  g_sh1);

    // independent prep
    prep_w<<<384, 256>>>(w0, w1);
    knn_kernel<<<dim3(NN / 256, BB), 256>>>(xyz1, xyz2);
    transpose_to_rows<false><<<dim3(SS / 32, C2V / 32, BB), dim3(32, 8)>>>(points2, p2t, C2V, SS, C2V, 0);
    transpose_to_rows<true ><<<dim3(NN / 32, C1V / 32, BB), dim3(32, 8)>>>(points1, xcat, C1V, NN, CCV, 0);
    interp_kernel<<<JJ / 8, 256>>>();
    // layer 0
    gemm_mma<CCV, 256, false><<<dim3(NRB, 4), 256>>>(xcat, w0t, b0, y0, nullptr, nullptr);
    bn_reduce<256><<<NRB, 256>>>(y0, p0s, p0q);
    finalize_bn<<<1, 256>>>(p0s, p0q, 256, gamma0, beta0, sc0, sh0);
    // layer 1 (BN0+ReLU folded into A load)
    gemm_mma<256, 128, true><<<dim3(NRB, 2), 256>>>(y0, w1t, b1, y1, sc0, sh0);
    bn_reduce<128><<<NRB, 128>>>(y1, p1s, p1q);
    finalize_bn<<<1, 128>>>(p1s, p1q, 128, gamma1, beta1, sc1, sh1);
    // output
    output_kernel<<<dim3(NN / 32, 128 / 32, BB), dim3(32, 8)>>>(out);
}

// round 6
// speedup vs baseline: 2.0339x; 1.0309x over previous
#include <cuda_runtime.h>
#include <cstdint>

#define BB 4
#define NN 8192
#define SS 2048
#define C1V 128
#define C2V 256
#define CCV 384           // C1+C2
#define JJ (BB*NN)        // 32768
#define NRB (JJ/128)      // 256 row blocks

// ---------------- device scratch ----------------
__device__ float g_p2t[BB*SS*C2V];                 // points2 transposed (B,S,C2)
__device__ float g_kd[2*JJ*3];                     // per-half knn candidate dists
__device__ int   g_ki[2*JJ*3];                     // per-half knn candidate idx
__device__ int   g_idx[JJ*3];
__device__ float g_wgt[JJ*3];
__device__ float g_y0[(size_t)JJ*256];             // layer0 pre-BN (f32)
__device__ float g_y1[(size_t)JJ*128];             // layer1 pre-BN (f32)
__device__ float g_w0t[256*384];                   // tf32-rounded weights
__device__ float g_w1t[128*256];
__device__ float g_p0s[NRB*256], g_p0q[NRB*256];
__device__ float g_p1s[NRB*128], g_p1q[NRB*128];
__device__ float g_sc0[256], g_sh0[256];
__device__ float g_sc1[128], g_sh1[128];

// ---------------- tf32 helpers (base ISA only) ----------------
__device__ __forceinline__ uint32_t f2tf32(float x) {
    uint32_t r;
    asm("cvt.rna.tf32.f32 %0, %1;" : "=r"(r) : "f"(x));
    return r;
}
__device__ __forceinline__ void mma16n8k8(float* c, const uint32_t* a, const uint32_t* b) {
    asm volatile(
        "mma.sync.aligned.m16n8k8.row.col.f32.tf32.tf32.f32 "
        "{%0,%1,%2,%3}, {%4,%5,%6,%7}, {%8,%9}, {%0,%1,%2,%3};"
        : "+f"(c[0]), "+f"(c[1]), "+f"(c[2]), "+f"(c[3])
        : "r"(a[0]), "r"(a[1]), "r"(a[2]), "r"(a[3]), "r"(b[0]), "r"(b[1]));
}

// ---------------- K1a: 3-NN over half of S ----------------
__global__ void knn_part(const float* __restrict__ xyz1, const float* __restrict__ xyz2) {
    __shared__ float4 pts[1024];
    const int b = blockIdx.y, half = blockIdx.z, soff = half * 1024;
    const float* x2 = xyz2 + (size_t)b * 3 * SS + soff;
    for (int s = threadIdx.x; s < 1024; s += blockDim.x) {
        float x = x2[s], y = x2[SS + s], z = x2[2 * SS + s];
        pts[s] = make_float4(x, y, z, x * x + y * y + z * z);
    }
    __syncthreads();
    const int n = blockIdx.x * blockDim.x + threadIdx.x;
    const float* x1 = xyz1 + (size_t)b * 3 * NN;
    const float qx = x1[n], qy = x1[NN + n], qz = x1[2 * NN + n];
    const float qn = qx * qx + qy * qy + qz * qz;
    float d0 = 3.4e38f, d1 = 3.4e38f, d2 = 3.4e38f;
    int   i0 = 0, i1 = 0, i2 = 0;
#pragma unroll 4
    for (int s = 0; s < 1024; ++s) {
        float4 p = pts[s];
        float dot = fmaf(qx, p.x, fmaf(qy, p.y, qz * p.z));
        float d = fmaf(-2.f, dot, qn + p.w);
        if (d < d2) {
            if (d < d1) {
                d2 = d1; i2 = i1;
                if (d < d0) { d1 = d0; i1 = i0; d0 = d; i0 = s; }
                else        { d1 = d;  i1 = s; }
            } else { d2 = d; i2 = s; }
        }
    }
    const int j = b * NN + n;
    const size_t o = ((size_t)half * JJ + j) * 3;
    g_kd[o + 0] = d0; g_kd[o + 1] = d1; g_kd[o + 2] = d2;
    g_ki[o + 0] = soff + i0; g_ki[o + 1] = soff + i1; g_ki[o + 2] = soff + i2;
}

// ---------------- K1b: merge two 3-NN candidate sets + weights ----------------
__global__ void knn_merge() {
    const int j = blockIdx.x * 256 + threadIdx.x;
    float ad[3], bd[3]; int ai3[3], bi3[3];
#pragma unroll
    for (int m = 0; m < 3; ++m) {
        ad[m] = g_kd[(size_t)j * 3 + m];           ai3[m] = g_ki[(size_t)j * 3 + m];
        bd[m] = g_kd[((size_t)JJ + j) * 3 + m];    bi3[m] = g_ki[((size_t)JJ + j) * 3 + m];
    }
    float md[3]; int mi[3];
    int ap = 0, bp = 0;
#pragma unroll
    for (int k = 0; k < 3; ++k) {
        if (ad[ap] <= bd[bp]) { md[k] = ad[ap]; mi[k] = ai3[ap]; ++ap; }
        else                  { md[k] = bd[bp]; mi[k] = bi3[bp]; ++bp; }
        if (ap > 2) ap = 2;   // clamp (only read, never picked past end)
        if (bp > 2) bp = 2;
    }
    float r0 = 1.f / (md[0] + 1e-8f), r1 = 1.f / (md[1] + 1e-8f), r2 = 1.f / (md[2] + 1e-8f);
    float inv = 1.f / (r0 + r1 + r2);
    g_idx[j * 3 + 0] = mi[0]; g_idx[j * 3 + 1] = mi[1]; g_idx[j * 3 + 2] = mi[2];
    g_wgt[j * 3 + 0] = r0 * inv; g_wgt[j * 3 + 1] = r1 * inv; g_wgt[j * 3 + 2] = r2 * inv;
}

// ---------------- K2: points2 (B,C2,S) -> p2t (B,S,C2) ----------------
__global__ void transpose_p2(const float* __restrict__ src) {
    __shared__ float tile[32][33];
    const int b = blockIdx.z;
    const int l0 = blockIdx.x * 32, c0 = blockIdx.y * 32;
    for (int i = threadIdx.y; i < 32; i += 8)
        tile[i][threadIdx.x] = src[((size_t)b * C2V + c0 + i) * SS + l0 + threadIdx.x];
    __syncthreads();
    for (int i = threadIdx.y; i < 32; i += 8)
        g_p2t[((size_t)b * SS + l0 + i) * C2V + c0 + threadIdx.x] = tile[threadIdx.x][i];
}

// ---------------- K-prep: round weights to tf32 ----------------
__global__ void prep_w(const float* __restrict__ w0, const float* __restrict__ w1) {
    int i = blockIdx.x * 256 + threadIdx.x;
    if (i < 256 * 384) g_w0t[i] = __uint_as_float(f2tf32(w0[i]));
    if (i < 128 * 256) g_w1t[i] = __uint_as_float(f2tf32(w1[i]));
}

// ==================== GEMM0: fused (transpose + interp) A-loader ====================
// Out = [xcat(J,384)] @ W0^T + b0, xcat materialized on the fly:
//   k <  128 : points1[b][k][n]          (channel-major read, transposed into smem)
//   k >= 128 : sum_m wgt[j][m] * p2t[b][idx[j][m]][k-128]
// As layout: k-major, stride 136 floats (bank = 8k+r mod 32, conflict-free fragments).
// Epilogue: bias + store y0 + per-CTA BN column partials.
__global__ __launch_bounds__(256) void gemm0_kernel(
    const float* __restrict__ P1, const float* __restrict__ W,
    const float* __restrict__ bias, float* __restrict__ out,
    float* __restrict__ psum, float* __restrict__ psq)
{
    __shared__ float As[16 * 136];
    __shared__ float Bs[64 * 20];
    __shared__ int   sidx[128 * 3];
    __shared__ float swgt[128 * 3];
    __shared__ float2 red_s[8 * 16], red_q[8 * 16];

    const int t = threadIdx.x, wid = t >> 5, lane = t & 31;
    const int j0 = blockIdx.x * 128, o0 = blockIdx.y * 64;
    const int b = j0 >> 13, n0 = j0 & (NN - 1);
    const int wm = (wid >> 1) * 32, wn = (wid & 1) * 32;
    const int lr = lane >> 2, lk = lane & 3;

    // stage idx/wgt for this CTA's 128 points
    if (t < 128) {
#pragma unroll
        for (int m = 0; m < 3; ++m) sidx[t * 3 + m] = g_idx[(size_t)(j0 + t) * 3 + m];
    } else {
        int r = t - 128;
#pragma unroll
        for (int m = 0; m < 3; ++m) swgt[r * 3 + m] = g_wgt[(size_t)(j0 + r) * 3 + m];
    }
    __syncthreads();

    // loader roles
    const int cA = t >> 4, gA = t & 15;      // case k<128: channel cA, point group gA
    const int rI = t >> 1, hI = t & 1;       // case k>=128: row rI, channel-half hI
    int   i3[3]; float w3[3];
#pragma unroll
    for (int m = 0; m < 3; ++m) { i3[m] = sidx[rI * 3 + m]; w3[m] = swgt[rI * 3 + m]; }
    const int brow = t >> 2, bkq = (t & 3) * 4;

    float acc[2][4][4];
#pragma unroll
    for (int mt = 0; mt < 2; ++mt)
#pragma unroll
        for (int nt = 0; nt < 4; ++nt)
#pragma unroll
            for (int i = 0; i < 4; ++i) acc[mt][nt][i] = 0.f;

    float4 rg[6]; float4 pb;
    auto ldc = [&](int c) {
        const int k0 = c * 16;
        pb = *(const float4*)&W[(size_t)(o0 + brow) * CCV + k0 + bkq];
        if (k0 < 128) {
            const float* bp = P1 + ((size_t)b * C1V + k0 + cA) * NN + n0 + gA * 4;
            rg[0] = *(const float4*)bp;
            rg[1] = *(const float4*)(bp + 64);
        } else {
            const int c8 = k0 - 128 + hI * 8;
#pragma unroll
            for (int m = 0; m < 3; ++m) {
                const float* pr = g_p2t + ((size_t)b * SS + i3[m]) * C2V + c8;
                rg[2 * m]     = *(const float4*)pr;
                rg[2 * m + 1] = *(const float4*)(pr + 4);
            }
        }
    };
    ldc(0);

    constexpr int NCHUNK = CCV / 16;   // 24
    for (int c = 0; c < NCHUNK; ++c) {
        const int k0 = c * 16;
        if (k0 < 128) {
            uint4 u0, u1;
            u0.x = f2tf32(rg[0].x); u0.y = f2tf32(rg[0].y); u0.z = f2tf32(rg[0].z); u0.w = f2tf32(rg[0].w);
            u1.x = f2tf32(rg[1].x); u1.y = f2tf32(rg[1].y); u1.z = f2tf32(rg[1].z); u1.w = f2tf32(rg[1].w);
            *(uint4*)&As[cA * 136 + gA * 4]      = u0;
            *(uint4*)&As[cA * 136 + 64 + gA * 4] = u1;
        } else {
            const float* f0 = (const float*)&rg[0];
            const float* f1 = (const float*)&rg[2];
            const float* f2p = (const float*)&rg[4];
#pragma unroll
            for (int i = 0; i < 8; ++i) {
                float v = w3[0] * f0[i] + w3[1] * f1[i] + w3[2] * f2p[i];
                As[(hI * 8 + i) * 136 + rI] = __uint_as_float(f2tf32(v));
            }
        }
        *(float4*)&Bs[brow * 20 + bkq] = pb;
        __syncthreads();
        if (c + 1 < NCHUNK) ldc(c + 1);

#pragma unroll
        for (int kk = 0; kk < 2; ++kk) {
            uint32_t af[2][4], bf[4][2];
            const int k = kk * 8 + lk;
#pragma unroll
            for (int mt = 0; mt < 2; ++mt) {
                const int r = wm + mt * 16 + lr;
                af[mt][0] = __float_as_uint(As[k * 136 + r]);
                af[mt][1] = __float_as_uint(As[k * 136 + r + 8]);
                af[mt][2] = __float_as_uint(As[(k + 4) * 136 + r]);
                af[mt][3] = __float_as_uint(As[(k + 4) * 136 + r + 8]);
            }
#pragma unroll
            for (int nt = 0; nt < 4; ++nt) {
                const int n = wn + nt * 8 + lr;
                bf[nt][0] = __float_as_uint(Bs[n * 20 + k]);
                bf[nt][1] = __float_as_uint(Bs[n * 20 + k + 4]);
            }
#pragma unroll
            for (int mt = 0; mt < 2; ++mt)
#pragma unroll
                for (int nt = 0; nt < 4; ++nt)
                    mma16n8k8(acc[mt][nt], af[mt], bf[nt]);
        }
        __syncthreads();
    }

    // epilogue: bias + store + BN column partials
    float2 sp[4], qp[4];
#pragma unroll
    for (int nt = 0; nt < 4; ++nt) { sp[nt] = make_float2(0.f, 0.f); qp[nt] = make_float2(0.f, 0.f); }
#pragma unroll
    for (int mt = 0; mt < 2; ++mt) {
        const int r0 = j0 + wm + mt * 16 + lr;
#pragma unroll
        for (int nt = 0; nt < 4; ++nt) {
            const int col = o0 + wn + nt * 8 + 2 * lk;
            const float b0 = bias[col], b1 = bias[col + 1];
            float v00 = acc[mt][nt][0] + b0, v01 = acc[mt][nt][1] + b1;
            float v10 = acc[mt][nt][2] + b0, v11 = acc[mt][nt][3] + b1;
            *(float2*)(out + (size_t)r0 * 256 + col)       = make_float2(v00, v01);
            *(float2*)(out + (size_t)(r0 + 8) * 256 + col) = make_float2(v10, v11);
            sp[nt].x += v00 + v10; sp[nt].y += v01 + v11;
            qp[nt].x += v00 * v00 + v10 * v10; qp[nt].y += v01 * v01 + v11 * v11;
        }
    }
#pragma unroll
    for (int nt = 0; nt < 4; ++nt) {
#pragma unroll
        for (int off = 16; off >= 4; off >>= 1) {
            sp[nt].x += __shfl_xor_sync(0xffffffffu, sp[nt].x, off);
            sp[nt].y += __shfl_xor_sync(0xffffffffu, sp[nt].y, off);
            qp[nt].x += __shfl_xor_sync(0xffffffffu, qp[nt].x, off);
            qp[nt].y += __shfl_xor_sync(0xffffffffu, qp[nt].y, off);
        }
    }
    if (lane < 4) {
#pragma unroll
        for (int nt = 0; nt < 4; ++nt) {
            red_s[wid * 16 + nt * 4 + lane] = sp[nt];
            red_q[wid * 16 + nt * 4 + lane] = qp[nt];
        }
    }
    __syncthreads();
    if (t < 64) {
        const int wnq = t >> 5, nt = (t >> 3) & 3, lkq = (t >> 1) & 3, hf = t & 1;
        float s = 0.f, q = 0.f;
#pragma unroll
        for (int wq = 0; wq < 4; ++wq) {
            const int w = wq * 2 + wnq;
            float2 a = red_s[w * 16 + nt * 4 + lkq];
            float2 c2 = red_q[w * 16 + nt * 4 + lkq];
            s += hf ? a.y : a.x;
            q += hf ? c2.y : c2.x;
        }
        psum[(size_t)blockIdx.x * 256 + o0 + t] = s;
        psq [(size_t)blockIdx.x * 256 + o0 + t] = q;
    }
}

// ==================== GEMM1: y1 = relu(bn0(y0)) @ W1^T + b1, + BN partials ====================
#define STRD 20
__global__ __launch_bounds__(256) void gemm1_kernel(
    const float* __restrict__ A, const float* __restrict__ W,
    const float* __restrict__ bias, float* __restrict__ out,
    const float* __restrict__ scale, const float* __restrict__ shift,
    float* __restrict__ psum, float* __restrict__ psq)
{
    __shared__ float As[128 * STRD];
    __shared__ float Bs[64 * STRD];
    __shared__ float2 red_s[8 * 16], red_q[8 * 16];

    const int t = threadIdx.x, wid = t >> 5, lane = t & 31;
    const int j0 = blockIdx.x * 128, o0 = blockIdx.y * 64;
    const int wm = (wid >> 1) * 32, wn = (wid & 1) * 32;
    const int lr = lane >> 2, lk = lane & 3;

    float acc[2][4][4];
#pragma unroll
    for (int mt = 0; mt < 2; ++mt)
#pragma unroll
        for (int nt = 0; nt < 4; ++nt)
#pragma unroll
            for (int i = 0; i < 4; ++i) acc[mt][nt][i] = 0.f;

    const int arow = t >> 2, akq = (t & 3) * 4;
    const int brow = t >> 2, bkq = (t & 3) * 4;

    float4 pa0, pa1, pb;
    {
        const float* a0 = A + (size_t)(j0 + arow) * 256 + akq;
        pa0 = *(const float4*)a0;
        pa1 = *(const float4*)(a0 + (size_t)64 * 256);
        pb  = *(const float4*)(W + (size_t)(o0 + brow) * 256 + bkq);
    }

    constexpr int NCHUNK = 256 / 16;
    for (int c = 0; c < NCHUNK; ++c) {
        float4 va0 = pa0, va1 = pa1;
        {
            const int kb = c * 16 + akq;
            float s0 = scale[kb], s1 = scale[kb+1], s2 = scale[kb+2], s3 = scale[kb+3];
            float h0 = shift[kb], h1 = shift[kb+1], h2 = shift[kb+2], h3 = shift[kb+3];
            va0.x = __uint_as_float(f2tf32(fmaxf(fmaf(va0.x, s0, h0), 0.f)));
            va0.y = __uint_as_float(f2tf32(fmaxf(fmaf(va0.y, s1, h1), 0.f)));
            va0.z = __uint_as_float(f2tf32(fmaxf(fmaf(va0.z, s2, h2), 0.f)));
            va0.w = __uint_as_float(f2tf32(fmaxf(fmaf(va0.w, s3, h3), 0.f)));
            va1.x = __uint_as_float(f2tf32(fmaxf(fmaf(va1.x, s0, h0), 0.f)));
            va1.y = __uint_as_float(f2tf32(fmaxf(fmaf(va1.y, s1, h1), 0.f)));
            va1.z = __uint_as_float(f2tf32(fmaxf(fmaf(va1.z, s2, h2), 0.f)));
            va1.w = __uint_as_float(f2tf32(fmaxf(fmaf(va1.w, s3, h3), 0.f)));
        }
        *(float4*)&As[arow * STRD + akq]        = va0;
        *(float4*)&As[(arow + 64) * STRD + akq] = va1;
        *(float4*)&Bs[brow * STRD + bkq]        = pb;
        __syncthreads();

        if (c + 1 < NCHUNK) {
            const int k0 = (c + 1) * 16;
            const float* a0 = A + (size_t)(j0 + arow) * 256 + k0 + akq;
            pa0 = *(const float4*)a0;
            pa1 = *(const float4*)(a0 + (size_t)64 * 256);
            pb  = *(const float4*)(W + (size_t)(o0 + brow) * 256 + k0 + bkq);
        }

#pragma unroll
        for (int kk = 0; kk < 2; ++kk) {
            uint32_t af[2][4], bf[4][2];
            const int k = kk * 8 + lk;
#pragma unroll
            for (int mt = 0; mt < 2; ++mt) {
                const int r = wm + mt * 16 + lr;
                af[mt][0] = __float_as_uint(As[r * STRD + k]);
                af[mt][1] = __float_as_uint(As[(r + 8) * STRD + k]);
                af[mt][2] = __float_as_uint(As[r * STRD + k + 4]);
                af[mt][3] = __float_as_uint(As[(r + 8) * STRD + k + 4]);
            }
#pragma unroll
            for (int nt = 0; nt < 4; ++nt) {
                const int n = wn + nt * 8 + lr;
                bf[nt][0] = __float_as_uint(Bs[n * STRD + k]);
                bf[nt][1] = __float_as_uint(Bs[n * STRD + k + 4]);
            }
#pragma unroll
            for (int mt = 0; mt < 2; ++mt)
#pragma unroll
                for (int nt = 0; nt < 4; ++nt)
                    mma16n8k8(acc[mt][nt], af[mt], bf[nt]);
        }
        __syncthreads();
    }

    float2 sp[4], qp[4];
#pragma unroll
    for (int nt = 0; nt < 4; ++nt) { sp[nt] = make_float2(0.f, 0.f); qp[nt] = make_float2(0.f, 0.f); }
#pragma unroll
    for (int mt = 0; mt < 2; ++mt) {
        const int r0 = j0 + wm + mt * 16 + lr;
#pragma unroll
        for (int nt = 0; nt < 4; ++nt) {
            const int col = o0 + wn + nt * 8 + 2 * lk;
            const float b0 = bias[col], b1 = bias[col + 1];
            float v00 = acc[mt][nt][0] + b0, v01 = acc[mt][nt][1] + b1;
            float v10 = acc[mt][nt][2] + b0, v11 = acc[mt][nt][3] + b1;
            *(float2*)(out + (size_t)r0 * 128 + col)       = make_float2(v00, v01);
            *(float2*)(out + (size_t)(r0 + 8) * 128 + col) = make_float2(v10, v11);
            sp[nt].x += v00 + v10; sp[nt].y += v01 + v11;
            qp[nt].x += v00 * v00 + v10 * v10; qp[nt].y += v01 * v01 + v11 * v11;
        }
    }
#pragma unroll
    for (int nt = 0; nt < 4; ++nt) {
#pragma unroll
        for (int off = 16; off >= 4; off >>= 1) {
            sp[nt].x += __shfl_xor_sync(0xffffffffu, sp[nt].x, off);
            sp[nt].y += __shfl_xor_sync(0xffffffffu, sp[nt].y, off);
            qp[nt].x += __shfl_xor_sync(0xffffffffu, qp[nt].x, off);
            qp[nt].y += __shfl_xor_sync(0xffffffffu, qp[nt].y, off);
        }
    }
    if (lane < 4) {
#pragma unroll
        for (int nt = 0; nt < 4; ++nt) {
            red_s[wid * 16 + nt * 4 + lane] = sp[nt];
            red_q[wid * 16 + nt * 4 + lane] = qp[nt];
        }
    }
    __syncthreads();
    if (t < 64) {
        const int wnq = t >> 5, nt = (t >> 3) & 3, lkq = (t >> 1) & 3, hf = t & 1;
        float s = 0.f, q = 0.f;
#pragma unroll
        for (int wq = 0; wq < 4; ++wq) {
            const int w = wq * 2 + wnq;
            float2 a = red_s[w * 16 + nt * 4 + lkq];
            float2 c2 = red_q[w * 16 + nt * 4 + lkq];
            s += hf ? a.y : a.x;
            q += hf ? c2.y : c2.x;
        }
        psum[(size_t)blockIdx.x * 128 + o0 + t] = s;
        psq [(size_t)blockIdx.x * 128 + o0 + t] = q;
    }
}

// ---------------- finalize BN scale/shift ----------------
__global__ void finalize_bn(const float* __restrict__ psum, const float* __restrict__ psq,
                            int C, const float* __restrict__ gamma, const float* __restrict__ beta,
                            float* __restrict__ scale, float* __restrict__ shift) {
    const int o = threadIdx.x;
    if (o >= C) return;
    float s = 0.f, q = 0.f;
    for (int r = 0; r < NRB; ++r) { s += psum[(size_t)r * C + o]; q += psq[(size_t)r * C + o]; }
    const float invn = 1.f / (float)JJ;
    float m = s * invn;
    float var = q * invn - m * m;
    float sc = gamma[o] * rsqrtf(var + 1e-5f);
    scale[o] = sc;
    shift[o] = beta[o] - m * sc;
}

// ---------------- output: BN1+ReLU + transpose to (B,128,N) ----------------
__global__ void output_kernel(float* __restrict__ out) {
    __shared__ float tile[32][33];
    const int b = blockIdx.z;
    const int n0 = blockIdx.x * 32, p0 = blockIdx.y * 32;
    const int tx = threadIdx.x;
    for (int i = threadIdx.y; i < 32; i += 8) {
        int p = p0 + tx, n = n0 + i;
        float v = g_y1[((size_t)b * NN + n) * 128 + p];
        tile[i][tx] = fmaxf(fmaf(v, g_sc1[p], g_sh1[p]), 0.f);
    }
    __syncthreads();
    for (int i = threadIdx.y; i < 32; i += 8)
        out[((size_t)(b * 128) + p0 + i) * NN + n0 + tx] = tile[tx][i];
}

// ---------------- launch ----------------
extern "C" void kernel_launch(void* const* d_in, const int* in_sizes, int n_in,
                              void* d_out, int out_size) {
    const float* xyz1    = (const float*)d_in[0];
    const float* xyz2    = (const float*)d_in[1];
    const float* points1 = (const float*)d_in[2];
    const float* points2 = (const float*)d_in[3];
    const float* w0      = (const float*)d_in[4];
    const float* b0      = (const float*)d_in[5];
    const float* gamma0  = (const float*)d_in[6];
    const float* beta0   = (const float*)d_in[7];
    const float* w1      = (const float*)d_in[8];
    const float* b1      = (const float*)d_in[9];
    const float* gamma1  = (const float*)d_in[10];
    const float* beta1   = (const float*)d_in[11];
    float* out = (float*)d_out;

    float *y0, *y1, *w0t, *w1t, *p0s, *p0q, *p1s, *p1q, *sc0, *sh0, *sc1, *sh1;
    cudaGetSymbolAddress((void**)&y0,   g_y0);
    cudaGetSymbolAddress((void**)&y1,   g_y1);
    cudaGetSymbolAddress((void**)&w0t,  g_w0t);
    cudaGetSymbolAddress((void**)&w1t,  g_w1t);
    cudaGetSymbolAddress((void**)&p0s,  g_p0s);
    cudaGetSymbolAddress((void**)&p0q,  g_p0q);
    cudaGetSymbolAddress((void**)&p1s,  g_p1s);
    cudaGetSymbolAddress((void**)&p1q,  g_p1q);
    cudaGetSymbolAddress((void**)&sc0,  g_sc0);
    cudaGetSymbolAddress((void**)&sh0,  g_sh0);
    cudaGetSymbolAddress((void**)&sc1,  g_sc1);
    cudaGetSymbolAddress((void**)&sh1,  g_sh1);

    // prep (independent)
    prep_w<<<384, 256>>>(w0, w1);
    knn_part<<<dim3(NN / 256, BB, 2), 256>>>(xyz1, xyz2);
    knn_merge<<<JJ / 256, 256>>>();
    transpose_p2<<<dim3(SS / 32, C2V / 32, BB), dim3(32, 8)>>>(points2);
    // layer 0 (fused transpose+interp A-loader, BN partials in epilogue)
    gemm0_kernel<<<dim3(NRB, 4), 256>>>(points1, w0t, b0, y0, p0s, p0q);
    finalize_bn<<<1, 256>>>(p0s, p0q, 256, gamma0, beta0, sc0, sh0);
    // layer 1 (BN0+ReLU folded into A load, BN partials in epilogue)
    gemm1_kernel<<<dim3(NRB, 2), 256>>>(y0, w1t, b1, y1, sc0, sh0, p1s, p1q);
    finalize_bn<<<1, 128>>>(p1s, p1q, 128, gamma1, beta1, sc1, sh1);
    // output: BN1+ReLU + transpose
    output_kernel<<<dim3(NN / 32, 128 / 32, BB), dim3(32, 8)>>>(out);
}

// round 7
// speedup vs baseline: 2.6185x; 1.2874x over previous
#include <cuda_runtime.h>
#include <cstdint>

#define BB 4
#define NN 8192
#define SS 2048
#define C1V 128
#define C2V 256
#define CCV 384
#define JJ (BB*NN)        // 32768
#define JZ (BB*SS)        // 8192
#define NRB (JJ/128)      // 256
#define NRZ (JZ/128)      // 64

// ---------------- device scratch ----------------
__device__ float g_p2t[(size_t)JZ*C2V];            // points2 transposed (B*S, C2)
__device__ float g_z[(size_t)JZ*256];              // Z = p2t @ W0b^T  (B*S, 256)
__device__ float g_kd[2*JJ*3];
__device__ int   g_ki[2*JJ*3];
__device__ int   g_idx[JJ*3];
__device__ float g_wgt[JJ*3];
__device__ float g_y0[(size_t)JJ*256];
__device__ float g_y1[(size_t)JJ*128];
__device__ float g_p0s[NRB*256], g_p0q[NRB*256];
__device__ float g_p1s[NRB*128], g_p1q[NRB*128];
__device__ float g_sc0[256], g_sh0[256];
__device__ float g_sc1[128], g_sh1[128];

// ---------------- helpers ----------------
__device__ __forceinline__ uint32_t f2tf32(float x) {
    uint32_t r;
    asm("cvt.rna.tf32.f32 %0, %1;" : "=r"(r) : "f"(x));
    return r;
}
__device__ __forceinline__ float rtf(float x) { return __uint_as_float(f2tf32(x)); }
__device__ __forceinline__ void mma16n8k8(float* c, const uint32_t* a, const uint32_t* b) {
    asm volatile(
        "mma.sync.aligned.m16n8k8.row.col.f32.tf32.tf32.f32 "
        "{%0,%1,%2,%3}, {%4,%5,%6,%7}, {%8,%9}, {%0,%1,%2,%3};"
        : "+f"(c[0]), "+f"(c[1]), "+f"(c[2]), "+f"(c[3])
        : "r"(a[0]), "r"(a[1]), "r"(a[2]), "r"(a[3]), "r"(b[0]), "r"(b[1]));
}

// ---------------- K: 3-NN over half of S ----------------
__global__ void knn_part(const float* __restrict__ xyz1, const float* __restrict__ xyz2) {
    __shared__ float4 pts[1024];
    const int b = blockIdx.y, half = blockIdx.z, soff = half * 1024;
    const float* x2 = xyz2 + (size_t)b * 3 * SS + soff;
    for (int s = threadIdx.x; s < 1024; s += blockDim.x) {
        float x = x2[s], y = x2[SS + s], z = x2[2 * SS + s];
        pts[s] = make_float4(x, y, z, x * x + y * y + z * z);
    }
    __syncthreads();
    const int n = blockIdx.x * blockDim.x + threadIdx.x;
    const float* x1 = xyz1 + (size_t)b * 3 * NN;
    const float qx = x1[n], qy = x1[NN + n], qz = x1[2 * NN + n];
    const float qn = qx * qx + qy * qy + qz * qz;
    float d0 = 3.4e38f, d1 = 3.4e38f, d2 = 3.4e38f;
    int   i0 = 0, i1 = 0, i2 = 0;
#pragma unroll 4
    for (int s = 0; s < 1024; ++s) {
        float4 p = pts[s];
        float dot = fmaf(qx, p.x, fmaf(qy, p.y, qz * p.z));
        float d = fmaf(-2.f, dot, qn + p.w);
        if (d < d2) {
            if (d < d1) {
                d2 = d1; i2 = i1;
                if (d < d0) { d1 = d0; i1 = i0; d0 = d; i0 = s; }
                else        { d1 = d;  i1 = s; }
            } else { d2 = d; i2 = s; }
        }
    }
    const int j = b * NN + n;
    const size_t o = ((size_t)half * JJ + j) * 3;
    g_kd[o + 0] = d0; g_kd[o + 1] = d1; g_kd[o + 2] = d2;
    g_ki[o + 0] = soff + i0; g_ki[o + 1] = soff + i1; g_ki[o + 2] = soff + i2;
}

// ---------------- K: merge candidates + weights ----------------
__global__ void knn_merge() {
    const int j = blockIdx.x * 256 + threadIdx.x;
    float ad[3], bd[3]; int ai3[3], bi3[3];
#pragma unroll
    for (int m = 0; m < 3; ++m) {
        ad[m] = g_kd[(size_t)j * 3 + m];           ai3[m] = g_ki[(size_t)j * 3 + m];
        bd[m] = g_kd[((size_t)JJ + j) * 3 + m];    bi3[m] = g_ki[((size_t)JJ + j) * 3 + m];
    }
    float md[3]; int mi[3];
    int ap = 0, bp = 0;
#pragma unroll
    for (int k = 0; k < 3; ++k) {
        if (ad[ap] <= bd[bp]) { md[k] = ad[ap]; mi[k] = ai3[ap]; ++ap; }
        else                  { md[k] = bd[bp]; mi[k] = bi3[bp]; ++bp; }
        if (ap > 2) ap = 2;
        if (bp > 2) bp = 2;
    }
    float r0 = 1.f / (md[0] + 1e-8f), r1 = 1.f / (md[1] + 1e-8f), r2 = 1.f / (md[2] + 1e-8f);
    float inv = 1.f / (r0 + r1 + r2);
    g_idx[j * 3 + 0] = mi[0]; g_idx[j * 3 + 1] = mi[1]; g_idx[j * 3 + 2] = mi[2];
    g_wgt[j * 3 + 0] = r0 * inv; g_wgt[j * 3 + 1] = r1 * inv; g_wgt[j * 3 + 2] = r2 * inv;
}

// ---------------- K: points2 (B,C2,S) -> (B*S, C2) ----------------
__global__ void transpose_p2(const float* __restrict__ src) {
    __shared__ float tile[32][33];
    const int b = blockIdx.z;
    const int l0 = blockIdx.x * 32, c0 = blockIdx.y * 32;
    for (int i = threadIdx.y; i < 32; i += 8)
        tile[i][threadIdx.x] = src[((size_t)b * C2V + c0 + i) * SS + l0 + threadIdx.x];
    __syncthreads();
    for (int i = threadIdx.y; i < 32; i += 8)
        g_p2t[((size_t)b * SS + l0 + i) * C2V + c0 + threadIdx.x] = tile[threadIdx.x][i];
}

// ======== point-major mma GEMM template: out = act(A) @ W^T (+bias) ========
// Block 128x64, 8 warps 32x32, k-chunk 16. W rounded to tf32 at staging.
// ACT: A -> relu(a*scale+shift) (rounded).  RNDA: A -> tf32 round only.
#define STRD 20
template<int KDIM, int NCOLS, bool ACT, bool RNDA, bool BNRED, bool HASBIAS>
__global__ __launch_bounds__(256) void gemm_pm(
    const float* __restrict__ A, const float* __restrict__ W, int wstride,
    const float* __restrict__ bias, float* __restrict__ out,
    const float* __restrict__ scale, const float* __restrict__ shift,
    float* __restrict__ psum, float* __restrict__ psq)
{
    __shared__ float As[128 * STRD];
    __shared__ float Bs[64 * STRD];
    __shared__ float2 red_s[8 * 16], red_q[8 * 16];

    const int t = threadIdx.x, wid = t >> 5, lane = t & 31;
    const int j0 = blockIdx.x * 128, o0 = blockIdx.y * 64;
    const int wm = (wid >> 1) * 32, wn = (wid & 1) * 32;
    const int lr = lane >> 2, lk = lane & 3;

    float acc[2][4][4];
#pragma unroll
    for (int mt = 0; mt < 2; ++mt)
#pragma unroll
        for (int nt = 0; nt < 4; ++nt)
#pragma unroll
            for (int i = 0; i < 4; ++i) acc[mt][nt][i] = 0.f;

    const int arow = t >> 2, akq = (t & 3) * 4;
    const int brow = t >> 2, bkq = (t & 3) * 4;

    float4 pa0, pa1, pb;
    {
        const float* a0 = A + (size_t)(j0 + arow) * KDIM + akq;
        pa0 = *(const float4*)a0;
        pa1 = *(const float4*)(a0 + (size_t)64 * KDIM);
        pb  = *(const float4*)(W + (size_t)(o0 + brow) * wstride + bkq);
    }

    constexpr int NCHUNK = KDIM / 16;
    for (int c = 0; c < NCHUNK; ++c) {
        float4 va0 = pa0, va1 = pa1, vb = pb;
        if (ACT) {
            const int kb = c * 16 + akq;
            float s0 = scale[kb], s1 = scale[kb+1], s2 = scale[kb+2], s3 = scale[kb+3];
            float h0 = shift[kb], h1 = shift[kb+1], h2 = shift[kb+2], h3 = shift[kb+3];
            va0.x = rtf(fmaxf(fmaf(va0.x, s0, h0), 0.f));
            va0.y = rtf(fmaxf(fmaf(va0.y, s1, h1), 0.f));
            va0.z = rtf(fmaxf(fmaf(va0.z, s2, h2), 0.f));
            va0.w = rtf(fmaxf(fmaf(va0.w, s3, h3), 0.f));
            va1.x = rtf(fmaxf(fmaf(va1.x, s0, h0), 0.f));
            va1.y = rtf(fmaxf(fmaf(va1.y, s1, h1), 0.f));
            va1.z = rtf(fmaxf(fmaf(va1.z, s2, h2), 0.f));
            va1.w = rtf(fmaxf(fmaf(va1.w, s3, h3), 0.f));
        } else if (RNDA) {
            va0.x = rtf(va0.x); va0.y = rtf(va0.y); va0.z = rtf(va0.z); va0.w = rtf(va0.w);
            va1.x = rtf(va1.x); va1.y = rtf(va1.y); va1.z = rtf(va1.z); va1.w = rtf(va1.w);
        }
        vb.x = rtf(vb.x); vb.y = rtf(vb.y); vb.z = rtf(vb.z); vb.w = rtf(vb.w);
        *(float4*)&As[arow * STRD + akq]        = va0;
        *(float4*)&As[(arow + 64) * STRD + akq] = va1;
        *(float4*)&Bs[brow * STRD + bkq]        = vb;
        __syncthreads();

        if (c + 1 < NCHUNK) {
            const int k0 = (c + 1) * 16;
            const float* a0 = A + (size_t)(j0 + arow) * KDIM + k0 + akq;
            pa0 = *(const float4*)a0;
            pa1 = *(const float4*)(a0 + (size_t)64 * KDIM);
            pb  = *(const float4*)(W + (size_t)(o0 + brow) * wstride + k0 + bkq);
        }

#pragma unroll
        for (int kk = 0; kk < 2; ++kk) {
            uint32_t af[2][4], bf[4][2];
            const int k = kk * 8 + lk;
#pragma unroll
            for (int mt = 0; mt < 2; ++mt) {
                const int r = wm + mt * 16 + lr;
                af[mt][0] = __float_as_uint(As[r * STRD + k]);
                af[mt][1] = __float_as_uint(As[(r + 8) * STRD + k]);
                af[mt][2] = __float_as_uint(As[r * STRD + k + 4]);
                af[mt][3] = __float_as_uint(As[(r + 8) * STRD + k + 4]);
            }
#pragma unroll
            for (int nt = 0; nt < 4; ++nt) {
                const int n = wn + nt * 8 + lr;
                bf[nt][0] = __float_as_uint(Bs[n * STRD + k]);
                bf[nt][1] = __float_as_uint(Bs[n * STRD + k + 4]);
            }
#pragma unroll
            for (int mt = 0; mt < 2; ++mt)
#pragma unroll
                for (int nt = 0; nt < 4; ++nt)
                    mma16n8k8(acc[mt][nt], af[mt], bf[nt]);
        }
        __syncthreads();
    }

    float2 sp[4], qp[4];
#pragma unroll
    for (int nt = 0; nt < 4; ++nt) { sp[nt] = make_float2(0.f, 0.f); qp[nt] = make_float2(0.f, 0.f); }
#pragma unroll
    for (int mt = 0; mt < 2; ++mt) {
        const int r0 = j0 + wm + mt * 16 + lr;
#pragma unroll
        for (int nt = 0; nt < 4; ++nt) {
            const int col = o0 + wn + nt * 8 + 2 * lk;
            float b0 = 0.f, b1 = 0.f;
            if (HASBIAS) { b0 = bias[col]; b1 = bias[col + 1]; }
            float v00 = acc[mt][nt][0] + b0, v01 = acc[mt][nt][1] + b1;
            float v10 = acc[mt][nt][2] + b0, v11 = acc[mt][nt][3] + b1;
            *(float2*)(out + (size_t)r0 * NCOLS + col)       = make_float2(v00, v01);
            *(float2*)(out + (size_t)(r0 + 8) * NCOLS + col) = make_float2(v10, v11);
            if (BNRED) {
                sp[nt].x += v00 + v10; sp[nt].y += v01 + v11;
                qp[nt].x += v00 * v00 + v10 * v10; qp[nt].y += v01 * v01 + v11 * v11;
            }
        }
    }
    if (BNRED) {
#pragma unroll
        for (int nt = 0; nt < 4; ++nt) {
#pragma unroll
            for (int off = 16; off >= 4; off >>= 1) {
                sp[nt].x += __shfl_xor_sync(0xffffffffu, sp[nt].x, off);
                sp[nt].y += __shfl_xor_sync(0xffffffffu, sp[nt].y, off);
                qp[nt].x += __shfl_xor_sync(0xffffffffu, qp[nt].x, off);
                qp[nt].y += __shfl_xor_sync(0xffffffffu, qp[nt].y, off);
            }
        }
        if (lane < 4) {
#pragma unroll
            for (int nt = 0; nt < 4; ++nt) {
                red_s[wid * 16 + nt * 4 + lane] = sp[nt];
                red_q[wid * 16 + nt * 4 + lane] = qp[nt];
            }
        }
        __syncthreads();
        if (t < 64) {
            const int wnq = t >> 5, nt = (t >> 3) & 3, lkq = (t >> 1) & 3, hf = t & 1;
            float s = 0.f, q = 0.f;
#pragma unroll
            for (int wq = 0; wq < 4; ++wq) {
                const int w = wq * 2 + wnq;
                float2 a = red_s[w * 16 + nt * 4 + lkq];
                float2 c2 = red_q[w * 16 + nt * 4 + lkq];
                s += hf ? a.y : a.x;
                q += hf ? c2.y : c2.x;
            }
            psum[(size_t)blockIdx.x * NCOLS + o0 + t] = s;
            psq [(size_t)blockIdx.x * NCOLS + o0 + t] = q;
        }
    }
}

// ======== GEMM0: y0 = T(points1) @ W0a^T + bias + gathered Z, + BN partials ========
// K=128, fused transpose A-loader (channel-major points1).
// Epilogue: cooperative gather of weighted Z rows into smem tile, add, store, BN partials.
// Dynamic smem layout (bytes):
//   As    [0, 8704)        16 k x 136 floats (k-major, conflict-free fragments)
//   Bs    [8704, 13824)    64 x 20
//   sidx  [13824, 15360)   128 x 3 int
//   swgt  [15360, 16896)   128 x 3 float
//   red   [16896, 20992)   2 x 8x16 float2
//   Zs    [20992, 55808)   128 x 68 floats
#define G0_SMEM 55808
__global__ __launch_bounds__(256) void gemm0_kernel(
    const float* __restrict__ P1, const float* __restrict__ W,
    const float* __restrict__ bias, float* __restrict__ out,
    float* __restrict__ psum, float* __restrict__ psq)
{
    extern __shared__ char dyn[];
    float*  As    = (float*)(dyn);
    float*  Bs    = (float*)(dyn + 8704);
    int*    sidx  = (int*)  (dyn + 13824);
    float*  swgt  = (float*)(dyn + 15360);
    float2* red_s = (float2*)(dyn + 16896);
    float2* red_q = red_s + 8 * 16;
    float*  Zs    = (float*)(dyn + 20992);

    const int t = threadIdx.x, wid = t >> 5, lane = t & 31;
    const int j0 = blockIdx.x * 128, o0 = blockIdx.y * 64;
    const int b = j0 >> 13, n0 = j0 & (NN - 1);
    const int wm = (wid >> 1) * 32, wn = (wid & 1) * 32;
    const int lr = lane >> 2, lk = lane & 3;

    if (t < 128) {
#pragma unroll
        for (int m = 0; m < 3; ++m) sidx[t * 3 + m] = g_idx[(size_t)(j0 + t) * 3 + m];
    } else {
        int r = t - 128;
#pragma unroll
        for (int m = 0; m < 3; ++m) swgt[r * 3 + m] = g_wgt[(size_t)(j0 + r) * 3 + m];
    }
    __syncthreads();

    const int cA = t >> 4, gA = t & 15;
    const int brow = t >> 2, bkq = (t & 3) * 4;

    float acc[2][4][4];
#pragma unroll
    for (int mt = 0; mt < 2; ++mt)
#pragma unroll
        for (int nt = 0; nt < 4; ++nt)
#pragma unroll
            for (int i = 0; i < 4; ++i) acc[mt][nt][i] = 0.f;

    float4 ra0, ra1, pb;
    {
        const float* bp = P1 + ((size_t)b * C1V + cA) * NN + n0 + gA * 4;
        ra0 = *(const float4*)bp;
        ra1 = *(const float4*)(bp + 64);
        pb  = *(const float4*)&W[(size_t)(o0 + brow) * CCV + bkq];
    }

    constexpr int NCHUNK = 8;   // K = 128
    for (int c = 0; c < NCHUNK; ++c) {
        uint4 u0, u1;
        u0.x = f2tf32(ra0.x); u0.y = f2tf32(ra0.y); u0.z = f2tf32(ra0.z); u0.w = f2tf32(ra0.w);
        u1.x = f2tf32(ra1.x); u1.y = f2tf32(ra1.y); u1.z = f2tf32(ra1.z); u1.w = f2tf32(ra1.w);
        *(uint4*)&As[cA * 136 + gA * 4]      = u0;
        *(uint4*)&As[cA * 136 + 64 + gA * 4] = u1;
        float4 vb = pb;
        vb.x = rtf(vb.x); vb.y = rtf(vb.y); vb.z = rtf(vb.z); vb.w = rtf(vb.w);
        *(float4*)&Bs[brow * 20 + bkq] = vb;
        __syncthreads();

        if (c + 1 < NCHUNK) {
            const int k0 = (c + 1) * 16;
            const float* bp = P1 + ((size_t)b * C1V + k0 + cA) * NN + n0 + gA * 4;
            ra0 = *(const float4*)bp;
            ra1 = *(const float4*)(bp + 64);
            pb  = *(const float4*)&W[(size_t)(o0 + brow) * CCV + k0 + bkq];
        }

#pragma unroll
        for (int kk = 0; kk < 2; ++kk) {
            uint32_t af[2][4], bf[4][2];
            const int k = kk * 8 + lk;
#pragma unroll
            for (int mt = 0; mt < 2; ++mt) {
                const int r = wm + mt * 16 + lr;
                af[mt][0] = __float_as_uint(As[k * 136 + r]);
                af[mt][1] = __float_as_uint(As[k * 136 + r + 8]);
                af[mt][2] = __float_as_uint(As[(k + 4) * 136 + r]);
                af[mt][3] = __float_as_uint(As[(k + 4) * 136 + r + 8]);
            }
#pragma unroll
            for (int nt = 0; nt < 4; ++nt) {
                const int n = wn + nt * 8 + lr;
                bf[nt][0] = __float_as_uint(Bs[n * 20 + k]);
                bf[nt][1] = __float_as_uint(Bs[n * 20 + k + 4]);
            }
#pragma unroll
            for (int mt = 0; mt < 2; ++mt)
#pragma unroll
                for (int nt = 0; nt < 4; ++nt)
                    mma16n8k8(acc[mt][nt], af[mt], bf[nt]);
        }
        __syncthreads();
    }

    // ---- gather weighted Z rows into Zs (coalesced: 4 threads per row cover 64 cols) ----
    {
        const int rg = t >> 2, qg = t & 3;
#pragma unroll
        for (int rr = 0; rr < 2; ++rr) {
            const int row = rg + rr * 64;
            const int s0 = sidx[row * 3 + 0], s1 = sidx[row * 3 + 1], s2 = sidx[row * 3 + 2];
            const float w0v = swgt[row * 3 + 0], w1v = swgt[row * 3 + 1], w2v = swgt[row * 3 + 2];
            const float* z0 = g_z + ((size_t)b * SS + s0) * 256 + o0 + qg * 16;
            const float* z1 = g_z + ((size_t)b * SS + s1) * 256 + o0 + qg * 16;
            const float* z2 = g_z + ((size_t)b * SS + s2) * 256 + o0 + qg * 16;
#pragma unroll
            for (int i = 0; i < 4; ++i) {
                float4 a = *(const float4*)(z0 + i * 4);
                float4 bq = *(const float4*)(z1 + i * 4);
                float4 cq = *(const float4*)(z2 + i * 4);
                float4 v;
                v.x = w0v * a.x + w1v * bq.x + w2v * cq.x;
                v.y = w0v * a.y + w1v * bq.y + w2v * cq.y;
                v.z = w0v * a.z + w1v * bq.z + w2v * cq.z;
                v.w = w0v * a.w + w1v * bq.w + w2v * cq.w;
                *(float4*)&Zs[row * 68 + qg * 16 + i * 4] = v;
            }
        }
    }
    __syncthreads();

    // ---- epilogue: bias + Zs + store + BN partials ----
    float2 sp[4], qp[4];
#pragma unroll
    for (int nt = 0; nt < 4; ++nt) { sp[nt] = make_float2(0.f, 0.f); qp[nt] = make_float2(0.f, 0.f); }
#pragma unroll
    for (int mt = 0; mt < 2; ++mt) {
        const int rloc = wm + mt * 16 + lr;
        const int r0 = j0 + rloc;
#pragma unroll
        for (int nt = 0; nt < 4; ++nt) {
            const int cloc = wn + nt * 8 + 2 * lk;
            const int col = o0 + cloc;
            const float b0 = bias[col], b1 = bias[col + 1];
            float v00 = acc[mt][nt][0] + b0 + Zs[rloc * 68 + cloc];
            float v01 = acc[mt][nt][1] + b1 + Zs[rloc * 68 + cloc + 1];
            float v10 = acc[mt][nt][2] + b0 + Zs[(rloc + 8) * 68 + cloc];
            float v11 = acc[mt][nt][3] + b1 + Zs[(rloc + 8) * 68 + cloc + 1];
            *(float2*)(out + (size_t)r0 * 256 + col)       = make_float2(v00, v01);
            *(float2*)(out + (size_t)(r0 + 8) * 256 + col) = make_float2(v10, v11);
            sp[nt].x += v00 + v10; sp[nt].y += v01 + v11;
            qp[nt].x += v00 * v00 + v10 * v10; qp[nt].y += v01 * v01 + v11 * v11;
        }
    }
#pragma unroll
    for (int nt = 0; nt < 4; ++nt) {
#pragma unroll
        for (int off = 16; off >= 4; off >>= 1) {
            sp[nt].x += __shfl_xor_sync(0xffffffffu, sp[nt].x, off);
            sp[nt].y += __shfl_xor_sync(0xffffffffu, sp[nt].y, off);
            qp[nt].x += __shfl_xor_sync(0xffffffffu, qp[nt].x, off);
            qp[nt].y += __shfl_xor_sync(0xffffffffu, qp[nt].y, off);
        }
    }
    if (lane < 4) {
#pragma unroll
        for (int nt = 0; nt < 4; ++nt) {
            red_s[wid * 16 + nt * 4 + lane] = sp[nt];
            red_q[wid * 16 + nt * 4 + lane] = qp[nt];
        }
    }
    __syncthreads();
    if (t < 64) {
        const int wnq = t >> 5, nt = (t >> 3) & 3, lkq = (t >> 1) & 3, hf = t & 1;
        float s = 0.f, q = 0.f;
#pragma unroll
        for (int wq = 0; wq < 4; ++wq) {
            const int w = wq * 2 + wnq;
            float2 a = red_s[w * 16 + nt * 4 + lkq];
            float2 c2 = red_q[w * 16 + nt * 4 + lkq];
            s += hf ? a.y : a.x;
            q += hf ? c2.y : c2.x;
        }
        psum[(size_t)blockIdx.x * 256 + o0 + t] = s;
        psq [(size_t)blockIdx.x * 256 + o0 + t] = q;
    }
}

// ---------------- finalize BN scale/shift ----------------
__global__ void finalize_bn(const float* __restrict__ psum, const float* __restrict__ psq,
                            int C, const float* __restrict__ gamma, const float* __restrict__ beta,
                            float* __restrict__ scale, float* __restrict__ shift) {
    const int o = threadIdx.x;
    if (o >= C) return;
    float s = 0.f, q = 0.f;
    for (int r = 0; r < NRB; ++r) { s += psum[(size_t)r * C + o]; q += psq[(size_t)r * C + o]; }
    const float invn = 1.f / (float)JJ;
    float m = s * invn;
    float var = q * invn - m * m;
    float sc = gamma[o] * rsqrtf(var + 1e-5f);
    scale[o] = sc;
    shift[o] = beta[o] - m * sc;
}

// ---------------- output: BN1+ReLU + transpose to (B,128,N) ----------------
__global__ void output_kernel(float* __restrict__ out) {
    __shared__ float tile[32][33];
    const int b = blockIdx.z;
    const int n0 = blockIdx.x * 32, p0 = blockIdx.y * 32;
    const int tx = threadIdx.x;
    for (int i = threadIdx.y; i < 32; i += 8) {
        int p = p0 + tx, n = n0 + i;
        float v = g_y1[((size_t)b * NN + n) * 128 + p];
        tile[i][tx] = fmaxf(fmaf(v, g_sc1[p], g_sh1[p]), 0.f);
    }
    __syncthreads();
    for (int i = threadIdx.y; i < 32; i += 8)
        out[((size_t)(b * 128) + p0 + i) * NN + n0 + tx] = tile[tx][i];
}

// ---------------- launch ----------------
extern "C" void kernel_launch(void* const* d_in, const int* in_sizes, int n_in,
                              void* d_out, int out_size) {
    const float* xyz1    = (const float*)d_in[0];
    const float* xyz2    = (const float*)d_in[1];
    const float* points1 = (const float*)d_in[2];
    const float* points2 = (const float*)d_in[3];
    const float* w0      = (const float*)d_in[4];
    const float* b0      = (const float*)d_in[5];
    const float* gamma0  = (const float*)d_in[6];
    const float* beta0   = (const float*)d_in[7];
    const float* w1      = (const float*)d_in[8];
    const float* b1      = (const float*)d_in[9];
    const float* gamma1  = (const float*)d_in[10];
    const float* beta1   = (const float*)d_in[11];
    float* out = (float*)d_out;

    float *p2t, *zbuf, *y0, *y1, *p0s, *p0q, *p1s, *p1q, *sc0, *sh0, *sc1, *sh1;
    cudaGetSymbolAddress((void**)&p2t,  g_p2t);
    cudaGetSymbolAddress((void**)&zbuf, g_z);
    cudaGetSymbolAddress((void**)&y0,   g_y0);
    cudaGetSymbolAddress((void**)&y1,   g_y1);
    cudaGetSymbolAddress((void**)&p0s,  g_p0s);
    cudaGetSymbolAddress((void**)&p0q,  g_p0q);
    cudaGetSymbolAddress((void**)&p1s,  g_p1s);
    cudaGetSymbolAddress((void**)&p1q,  g_p1q);
    cudaGetSymbolAddress((void**)&sc0,  g_sc0);
    cudaGetSymbolAddress((void**)&sh0,  g_sh0);
    cudaGetSymbolAddress((void**)&sc1,  g_sc1);
    cudaGetSymbolAddress((void**)&sh1,  g_sh1);

    cudaFuncSetAttribute(gemm0_kernel, cudaFuncAttributeMaxDynamicSharedMemorySize, G0_SMEM);

    // 1: transpose points2
    transpose_p2<<<dim3(SS / 32, C2V / 32, BB), dim3(32, 8)>>>(points2);
    // 2-3: knn
    knn_part<<<dim3(NN / 256, BB, 2), 256>>>(xyz1, xyz2);
    knn_merge<<<JJ / 256, 256>>>();
    // 4: Z = p2t @ W0b^T  (W0b = w0 cols 128..383)  -- profiled slot
    gemm_pm<256, 256, false, true, false, false><<<dim3(NRZ, 4), 256>>>(
        p2t, w0 + 128, CCV, nullptr, zbuf, nullptr, nullptr, nullptr, nullptr);
    // 5: y0 = T(points1) @ W0a^T + b0 + gather(Z), + BN partials
    gemm0_kernel<<<dim3(NRB, 4), 256, G0_SMEM>>>(points1, w0, b0, y0, p0s, p0q);
    // 6: BN0 finalize
    finalize_bn<<<1, 256>>>(p0s, p0q, 256, gamma0, beta0, sc0, sh0);
    // 7: y1 = relu(bn0(y0)) @ W1^T + b1, + BN partials
    gemm_pm<256, 128, true, false, true, true><<<dim3(NRB, 2), 256>>>(
        y0, w1, 256, b1, y1, sc0, sh0, p1s, p1q);
    // 8: BN1 finalize
    finalize_bn<<<1, 128>>>(p1s, p1q, 128, gamma1, beta1, sc1, sh1);
    // 9: output transpose + BN1 + ReLU
    output_kernel<<<dim3(NN / 32, 128 / 32, BB), dim3(32, 8)>>>(out);
}